// round 16
// baseline (speedup 1.0000x reference)
#include <cuda_runtime.h>
#include <cuda_bf16.h>
#include <stdint.h>
#include <math.h>

#define NTOK 32768
#define BATCH 8
#define SEQ 4096
#define DDIM 1024
#define HDIM 2048
#define MAXK 64

#define BM 128
#define BN 256
#define BK 128
#define NHC 8
#define UNIT_KSTAGES (DDIM / BK)    // 8

// smem: 2 stages of [A 128x272B = 34816][B 256x272B = 69632] = 104448 each
#define STAGE_BYTES 104448
#define NPIPE 2
#define B1S_OFF  (NPIPE * STAGE_BYTES)      // 208896
#define W2S_OFF  (B1S_OFF + 1024)
#define RED_OFF  (W2S_OFF + 1024)
#define DYN_SMEM (RED_OFF + 2048)           // 212992

#define BANDW  0.06f
#define MAXBAND 64

// ---------------- scratch ----------------
static __device__ float g_part[(size_t)NTOK * NHC];
static __device__ float g_mask[NTOK];
static __device__ __nv_bfloat16 g_Xhi[(size_t)NTOK * DDIM];
static __device__ __nv_bfloat16 g_Whi[(size_t)HDIM * DDIM];  // n-major (transposed)
static __device__ int   g_band_idx[BATCH * MAXBAND];
static __device__ float g_band_partial[BATCH * MAXBAND * 16];
static __device__ int   g_bandcnt[BATCH];
static __device__ int   g_bandsel[BATCH];

// ---------------- PTX helpers ----------------
__device__ __forceinline__ uint32_t smem_u32(const void* p) {
  uint32_t a;
  asm("{ .reg .u64 t; cvta.to.shared.u64 t, %1; cvt.u32.u64 %0, t; }" : "=r"(a) : "l"(p));
  return a;
}
__device__ __forceinline__ void cp16(uint32_t saddr, const void* gaddr) {
  asm volatile("cp.async.cg.shared.global [%0], [%1], 16;" :: "r"(saddr), "l"(gaddr));
}
#define CP_COMMIT() asm volatile("cp.async.commit_group;" ::: "memory")
#define CP_WAIT0()  asm volatile("cp.async.wait_group 0;" ::: "memory")

__device__ __forceinline__ void ldsm4(uint32_t* r, uint32_t addr) {
  asm volatile("ldmatrix.sync.aligned.m8n8.x4.shared.b16 {%0,%1,%2,%3}, [%4];"
               : "=r"(r[0]), "=r"(r[1]), "=r"(r[2]), "=r"(r[3]) : "r"(addr));
}
__device__ __forceinline__ void ldsm_b2(uint32_t (*b)[2], uint32_t addr) {
  uint32_t r[4];
  ldsm4(r, addr);
  b[0][0] = r[0]; b[0][1] = r[2];
  b[1][0] = r[1]; b[1][1] = r[3];
}
__device__ __forceinline__ void mma16816(float* c, const uint32_t* a, const uint32_t* b) {
  asm volatile("mma.sync.aligned.m16n8k16.row.col.f32.bf16.bf16.f32 "
               "{%0,%1,%2,%3}, {%4,%5,%6,%7}, {%8,%9}, {%0,%1,%2,%3};"
               : "+f"(c[0]), "+f"(c[1]), "+f"(c[2]), "+f"(c[3])
               : "r"(a[0]), "r"(a[1]), "r"(a[2]), "r"(a[3]), "r"(b[0]), "r"(b[1]));
}

// monotone float->uint key (larger float -> larger key)
__device__ __forceinline__ uint32_t f2key(float f) {
  uint32_t b = __float_as_uint(f);
  return (b & 0x80000000u) ? ~b : (b | 0x80000000u);
}
__device__ __forceinline__ float key2f(uint32_t k) {
  uint32_t b = (k & 0x80000000u) ? (k & 0x7FFFFFFFu) : ~k;
  return __uint_as_float(b);
}

// ---------------- threefry2x32-20 (JAX) ----------------
__host__ __device__ __forceinline__ void tf2x32(uint32_t k0, uint32_t k1,
                                                uint32_t x0, uint32_t x1,
                                                uint32_t* o0, uint32_t* o1) {
  uint32_t ks2 = k0 ^ k1 ^ 0x1BD11BDAu;
#define ROTL(v, d) (((v) << (d)) | ((v) >> (32 - (d))))
#define RND(r) { x0 += x1; x1 = ROTL(x1, r); x1 ^= x0; }
  x0 += k0; x1 += k1;
  RND(13) RND(15) RND(26) RND(6)
  x0 += k1; x1 += ks2 + 1u;
  RND(17) RND(29) RND(16) RND(24)
  x0 += ks2; x1 += k0 + 2u;
  RND(13) RND(15) RND(26) RND(6)
  x0 += k0; x1 += k1 + 3u;
  RND(17) RND(29) RND(16) RND(24)
  x0 += k1; x1 += ks2 + 4u;
  RND(13) RND(15) RND(26) RND(6)
  x0 += ks2; x1 += k0 + 5u;
#undef RND
#undef ROTL
  *o0 = x0; *o1 = x1;
}
__device__ __forceinline__ float gumbel_at(uint32_t k0, uint32_t k1, uint32_t idx) {
  uint32_t a, b;
  tf2x32(k0, k1, 0u, idx, &a, &b);
  uint32_t bits = a ^ b;
  float u = __uint_as_float((bits >> 9) | 0x3f800000u) - 1.0f;
  u = u + 1e-8f;
  u = fmaxf(1e-8f, u);
  return -logf(-logf(u));
}

// ---------------- conversion kernels (hi only) ----------------
__global__ __launch_bounds__(256) void convX_kernel(const float* __restrict__ X) {
  size_t i = (size_t)blockIdx.x * 256 + threadIdx.x;   // float4 index
  float4 v = ((const float4*)X)[i];
  __nv_bfloat162* H = (__nv_bfloat162*)g_Xhi;
  H[i * 2]     = __nv_bfloat162(__float2bfloat16(v.x), __float2bfloat16(v.y));
  H[i * 2 + 1] = __nv_bfloat162(__float2bfloat16(v.z), __float2bfloat16(v.w));
}

__global__ __launch_bounds__(256) void convW_kernel(const float* __restrict__ W1) {
  __shared__ float s[32][33];
  int n0 = blockIdx.x * 32;
  int k0 = blockIdx.y * 32;
  int tx = threadIdx.x & 31, ty = threadIdx.x >> 5;   // ty 0..7
#pragma unroll
  for (int j = 0; j < 4; j++) {
    int k = k0 + ty + j * 8;
    s[ty + j * 8][tx] = W1[(size_t)k * HDIM + n0 + tx];
  }
  __syncthreads();
#pragma unroll
  for (int j = 0; j < 4; j++) {
    int n = n0 + ty + j * 8;
    g_Whi[(size_t)n * DDIM + k0 + tx] = __float2bfloat16(s[tx][ty + j * 8]);
  }
}

// ---------------- 1-pass bf16 HMMA GEMM -> per-chunk partial logits ----------------
// grid = 2048 units (256 row-blocks x 8 h-chunks), 512 threads, warp tile 32x64.
// BK=128, 8 k-stages per unit, 2-stage cp.async pipeline (104KB stages).
__global__ __launch_bounds__(512, 1)
void gemm_logits_kernel(const float* __restrict__ b1, const float* __restrict__ W2) {
  extern __shared__ char smem[];
  const uint32_t sb = smem_u32(smem);
  const int tid = threadIdx.x;
  const int lane = tid & 31;
  const int wid = tid >> 5;
  const int wm = wid & 3;           // 0..3 (m, 32-row slices)
  const int wn = wid >> 2;          // 0..3 (n, 64-col slices)
  const int row0 = (blockIdx.x >> 3) * BM;
  const int hc = blockIdx.x & 7;

  float* b1s = (float*)(smem + B1S_OFF);
  float* w2s = (float*)(smem + W2S_OFF);
  float* red = (float*)(smem + RED_OFF);

  // loader: A 2048 chunks (4/thread), B 4096 chunks (8/thread); 16B chunks
  const int rowA = tid >> 2, cA = (tid & 3) * 64;     // A: row 0..127, 64B group
  const int rowB = tid >> 1, cB = (tid & 1) * 128;    // B: row 0..255, 128B group
  const char* pXb = (const char*)g_Xhi + (((size_t)(row0 + rowA)) << 11) + cA;
  const char* pWb = (const char*)g_Whi + (((size_t)(hc * BN + rowB)) << 11) + cB;
  const uint32_t sAo = (uint32_t)(rowA * 272 + cA);
  const uint32_t sBo = (uint32_t)(34816 + rowB * 272 + cB);

#define ISSUE_STAGE(stgbase, ks) do {                                        \
    const uint32_t _stg = (stgbase);                                         \
    const size_t _ko = ((size_t)(ks)) << 8;                                  \
    _Pragma("unroll")                                                        \
    for (int j = 0; j < 4; j++)                                              \
      cp16(_stg + sAo + j * 16, pXb + _ko + j * 16);                         \
    _Pragma("unroll")                                                        \
    for (int j = 0; j < 8; j++)                                              \
      cp16(_stg + sBo + j * 16, pWb + _ko + j * 16);                         \
  } while (0)

  // prefetch stage 0
  ISSUE_STAGE(sb, 0);
  CP_COMMIT();

  // stage this chunk's b1/W2 (256 floats each); published by loop barrier
  if (tid < 256) {
    b1s[tid] = b1[hc * BN + tid];
    w2s[tid] = W2[hc * BN + tid];
  }

  float C[2][8][4];
#pragma unroll
  for (int mi = 0; mi < 2; mi++)
#pragma unroll
    for (int ni = 0; ni < 8; ni++)
#pragma unroll
      for (int j = 0; j < 4; j++) C[mi][ni][j] = 0.0f;

  const int lr = lane & 15, lh = lane >> 4;
  const uint32_t aOff = (uint32_t)((wm * 32 + lr) * 272 + lh * 16);
  const uint32_t bOff = (uint32_t)(34816 + (wn * 64 + lr) * 272 + lh * 16);

  for (int s = 0; s < UNIT_KSTAGES; s++) {
    CP_WAIT0();
    __syncthreads();   // publish buf s; certify compute(s-1) done
    if (s + 1 < UNIT_KSTAGES) {
      ISSUE_STAGE(sb + ((s + 1) & 1) * STAGE_BYTES, s + 1);
      CP_COMMIT();
    }

    const uint32_t aB = sb + (s & 1) * STAGE_BYTES + aOff;
    const uint32_t bB = sb + (s & 1) * STAGE_BYTES + bOff;
#pragma unroll
    for (int k16 = 0; k16 < 8; k16++) {
      const uint32_t kofs = (uint32_t)(k16 * 32);
      uint32_t ah[2][4], bb0[4][2], bb1[4][2];
      ldsm4(ah[0], aB + kofs);
      ldsm4(ah[1], aB + 16 * 272 + kofs);
      ldsm_b2(bb0 + 0, bB + kofs);
      ldsm_b2(bb0 + 2, bB + 16 * 272 + kofs);
      ldsm_b2(bb1 + 0, bB + 2 * (16 * 272) + kofs);
      ldsm_b2(bb1 + 2, bB + 3 * (16 * 272) + kofs);
#pragma unroll
      for (int mi = 0; mi < 2; mi++)
#pragma unroll
        for (int ni = 0; ni < 4; ni++) mma16816(C[mi][ni], ah[mi], bb0[ni]);
#pragma unroll
      for (int mi = 0; mi < 2; mi++)
#pragma unroll
        for (int ni = 0; ni < 4; ni++) mma16816(C[mi][ni + 4], ah[mi], bb1[ni]);
    }
  }

  // epilogue: bias -> relu -> *W2 -> per-row partial for this h-chunk
  float lacc[4] = {0.0f, 0.0f, 0.0f, 0.0f};
  const int colbase = wn * 64 + (lane & 3) * 2;
#pragma unroll
  for (int ni = 0; ni < 8; ni++) {
    const int c0 = colbase + ni * 8;
    const float b10 = b1s[c0], b11 = b1s[c0 + 1];
    const float w20 = w2s[c0], w21 = w2s[c0 + 1];
#pragma unroll
    for (int mi = 0; mi < 2; mi++) {
      lacc[mi * 2 + 0] += fmaxf(C[mi][ni][0] + b10, 0.0f) * w20
                        + fmaxf(C[mi][ni][1] + b11, 0.0f) * w21;
      lacc[mi * 2 + 1] += fmaxf(C[mi][ni][2] + b10, 0.0f) * w20
                        + fmaxf(C[mi][ni][3] + b11, 0.0f) * w21;
    }
  }
#pragma unroll
  for (int j = 0; j < 4; j++) {
    lacc[j] += __shfl_xor_sync(0xFFFFFFFFu, lacc[j], 1);
    lacc[j] += __shfl_xor_sync(0xFFFFFFFFu, lacc[j], 2);
  }
  __syncthreads();
  if ((lane & 3) == 0) {
    const int r = lane >> 2;
    red[wn * 128 + wm * 32 + r]      = lacc[0];
    red[wn * 128 + wm * 32 + 8 + r]  = lacc[1];
    red[wn * 128 + wm * 32 + 16 + r] = lacc[2];
    red[wn * 128 + wm * 32 + 24 + r] = lacc[3];
  }
  __syncthreads();
  if (tid < BM)
    g_part[(size_t)(row0 + tid) * NHC + hc] =
        (red[tid] + red[128 + tid]) + (red[256 + tid] + red[384 + tid]);
}

// ---------------- top-k (radix select) + k-select fold + band extraction ----------------
__global__ __launch_bounds__(1024)
void topk_kernel(const float* __restrict__ k_logits, float* __restrict__ out_ek,
                 float* __restrict__ out_mask,
                 uint32_t r1k0, uint32_t r1k1, uint32_t r2k0, uint32_t r2k1) {
  __shared__ float vals[SEQ];
  __shared__ unsigned char msk[SEQ];
  __shared__ float zk[MAXK];
  __shared__ int hist[256];
  __shared__ int s_digit, s_acc, s_k;
  __shared__ int tieIdx[64];
  __shared__ int tieCnt;
  __shared__ int scnt, scsel;
  const int row = blockIdx.x;
  const int tid = threadIdx.x;

  if (tid < MAXK) zk[tid] = k_logits[tid] + gumbel_at(r1k0, r1k1, (uint32_t)tid);

#pragma unroll
  for (int j = 0; j < 4; j++) {
    int i = tid + j * 1024;
    uint32_t idx = (uint32_t)(row * SEQ + i);
    const float4* pp = (const float4*)&g_part[(size_t)idx * NHC];
    float4 a = pp[0], b = pp[1];
    float s = ((a.x + a.y) + (a.z + a.w)) + ((b.x + b.y) + (b.z + b.w));
    vals[i] = s + gumbel_at(r2k0, r2k1, idx);
    msk[i] = 0;
  }
  if (tid == 0) { scnt = 0; scsel = 0; tieCnt = 0; }
  __syncthreads();

  if (tid == 0) {
    float m = -INFINITY; int am = 0;
    for (int i = 0; i < MAXK; i++) if (zk[i] > m) { m = zk[i]; am = i; }
    float ssum = 0.0f, e[MAXK];
    for (int i = 0; i < MAXK; i++) { e[i] = expf(zk[i] - m); ssum += e[i]; }
    float ek = 0.0f;
    for (int i = 0; i < MAXK; i++) ek += (e[i] / ssum) * (float)(i + 1);
    out_ek[0] = ek;      // all 8 blocks write the same value
    s_k = am + 1;
  }
  __syncthreads();
  const int k = s_k;

  // 4-round MSB radix select for the k-th largest key
  uint32_t prefix = 0;
  int kk = k;
  for (int shift = 24; shift >= 0; shift -= 8) {
    if (tid < 256) hist[tid] = 0;
    __syncthreads();
    const uint32_t pmask = (shift == 24) ? 0u : (0xFFFFFFFFu << (shift + 8));
#pragma unroll
    for (int j = 0; j < 4; j++) {
      uint32_t key = f2key(vals[tid + j * 1024]);
      if ((key & pmask) == prefix) atomicAdd(&hist[(key >> shift) & 0xFF], 1);
    }
    __syncthreads();
    if (tid == 0) {
      int acc = 0, d = 255;
      for (; d > 0; d--) {
        if (acc + hist[d] >= kk) break;
        acc += hist[d];
      }
      s_digit = d; s_acc = acc;
    }
    __syncthreads();
    kk -= s_acc;
    prefix |= ((uint32_t)s_digit) << shift;
    __syncthreads();
  }
  const uint32_t thKey = prefix;
  const float sAk = key2f(thKey);

  // mark strict winners; collect ties (== threshold key)
#pragma unroll
  for (int j = 0; j < 4; j++) {
    int i = tid + j * 1024;
    uint32_t key = f2key(vals[i]);
    if (key > thKey) msk[i] = 1;
    else if (key == thKey) {
      int p = atomicAdd(&tieCnt, 1);
      if (p < 64) tieIdx[p] = i;
    }
  }
  __syncthreads();
  if (tid == 0) {
    int tc = tieCnt < 64 ? tieCnt : 64;
    for (int sel = 0; sel < kk; sel++) {
      int best = SEQ, bp = -1;
      for (int p = 0; p < tc; p++)
        if (tieIdx[p] < best) { best = tieIdx[p]; bp = p; }
      if (bp >= 0) { msk[best] = 1; tieIdx[bp] = SEQ; }
    }
  }
  __syncthreads();

  // write masks + band capture
#pragma unroll
  for (int j = 0; j < 4; j++) {
    int i = tid + j * 1024;
    float m = (float)msk[i];
    out_mask[row * SEQ + i] = m;
    g_mask[row * SEQ + i] = m;
    if (fabsf(vals[i] - sAk) <= BANDW) {
      int p = atomicAdd(&scnt, 1);
      if (p < MAXBAND) g_band_idx[row * MAXBAND + p] = i;
      if (msk[i]) atomicAdd(&scsel, 1);
    }
  }
  __syncthreads();
  if (tid == 0) {
    g_bandcnt[row] = scnt < MAXBAND ? scnt : MAXBAND;
    g_bandsel[row] = scsel;
  }
}

// ---------------- refine: exact fp32 logits for band tokens ----------------
__global__ __launch_bounds__(256)
void refine_kernel(const float* __restrict__ X, const float* __restrict__ W1,
                   const float* __restrict__ b1, const float* __restrict__ W2) {
  const int jc = blockIdx.x, row = blockIdx.y, c0 = blockIdx.z * 16;
  const int cnt = g_bandcnt[row];
  if (c0 >= cnt) return;
  const int tid = threadIdx.x;
  const int tc = tid & 15, tj = tid >> 4;

  __shared__ int stok[16];
  __shared__ float Xs[16][33];
  __shared__ float Ws[32][132];
  __shared__ float part[16][17];

  if (tid < 16)
    stok[tid] = (c0 + tid < cnt) ? row * SEQ + g_band_idx[row * MAXBAND + c0 + tid]
                                 : row * SEQ;
  __syncthreads();

  float acc[8];
#pragma unroll
  for (int u = 0; u < 8; u++) acc[u] = 0.0f;

  for (int k0 = 0; k0 < DDIM; k0 += 32) {
#pragma unroll
    for (int p = 0; p < 2; p++) {
      int e = tid + p * 256;
      int c = e >> 5, kk = e & 31;
      Xs[c][kk] = X[(size_t)stok[c] * DDIM + k0 + kk];
    }
#pragma unroll
    for (int q = 0; q < 16; q++) {
      int f = tid + q * 256;
      int kk = f >> 7, jj = f & 127;
      Ws[kk][jj] = W1[(size_t)(k0 + kk) * HDIM + jc * 128 + jj];
    }
    __syncthreads();
#pragma unroll
    for (int kk = 0; kk < 32; kk++) {
      float x = Xs[tc][kk];
      const float4* wrow = (const float4*)&Ws[kk][tj * 8];
      float4 w0 = wrow[0], w1 = wrow[1];
      acc[0] = fmaf(x, w0.x, acc[0]); acc[1] = fmaf(x, w0.y, acc[1]);
      acc[2] = fmaf(x, w0.z, acc[2]); acc[3] = fmaf(x, w0.w, acc[3]);
      acc[4] = fmaf(x, w1.x, acc[4]); acc[5] = fmaf(x, w1.y, acc[5]);
      acc[6] = fmaf(x, w1.z, acc[6]); acc[7] = fmaf(x, w1.w, acc[7]);
    }
    __syncthreads();
  }

  float contrib = 0.0f;
#pragma unroll
  for (int u = 0; u < 8; u++) {
    int j = jc * 128 + tj * 8 + u;
    float h = acc[u] + b1[j];
    contrib += fmaxf(h, 0.0f) * W2[j];
  }
  part[tj][tc] = contrib;
  __syncthreads();
  if (tid < 16) {
    float s = 0.0f;
#pragma unroll
    for (int t = 0; t < 16; t++) s += part[t][tid];
    if (c0 + tid < cnt)
      g_band_partial[(row * MAXBAND + c0 + tid) * 16 + jc] = s;
  }
}

// ---------------- fixup: re-rank band by exact values ----------------
__global__ __launch_bounds__(64)
void fixup_kernel(float* __restrict__ out_mask, uint32_t r2k0, uint32_t r2k1) {
  const int row = blockIdx.x, t = threadIdx.x;
  const int cnt = g_bandcnt[row], csel = g_bandsel[row];
  __shared__ float sv[64], svv[64];
  __shared__ int si[64];

  float v = -INFINITY; int idx = -1;
  if (t < cnt) {
    idx = g_band_idx[row * MAXBAND + t];
    float s = 0.0f;
#pragma unroll
    for (int c = 0; c < 16; c++) s += g_band_partial[(row * MAXBAND + t) * 16 + c];
    v = s + gumbel_at(r2k0, r2k1, (uint32_t)(row * SEQ + idx));
  }
  svv[t] = v;
  __syncthreads();

  int chosen = 0;
  for (int it = 0; it < csel; it++) {
    sv[t] = svv[t]; si[t] = t;
    __syncthreads();
    for (int off = 32; off > 0; off >>= 1) {
      if (t < off) {
        if (sv[t + off] > sv[t] || (sv[t + off] == sv[t] && si[t + off] < si[t])) {
          sv[t] = sv[t + off]; si[t] = si[t + off];
        }
      }
      __syncthreads();
    }
    if (t == si[0]) { chosen = 1; svv[t] = -INFINITY; }
    __syncthreads();
  }

  if (t < cnt) {
    float m = (float)chosen;
    out_mask[row * SEQ + idx] = m;
    g_mask[row * SEQ + idx] = m;
  }
}

// ---------------- scatter ----------------
__global__ __launch_bounds__(256)
void scatter_kernel(const float* __restrict__ X, float* __restrict__ out) {
  const int t = blockIdx.x;
  const int tid = threadIdx.x;
  const float m = g_mask[t];
  float4* dst = (float4*)(out + (size_t)t * DDIM);
  if (m != 0.0f) {
    const float4* src = (const float4*)(X + (size_t)t * DDIM);
    dst[tid] = src[tid];
  } else {
    dst[tid] = make_float4(0.0f, 0.0f, 0.0f, 0.0f);
  }
}

// ---------------- launch ----------------
extern "C" void kernel_launch(void* const* d_in, const int* in_sizes, int n_in,
                              void* d_out, int out_size) {
  const float* X  = (const float*)d_in[0];
  const float* W1 = (const float*)d_in[1];
  const float* b1 = (const float*)d_in[2];
  const float* W2 = (const float*)d_in[3];
  const float* kl = (const float*)d_in[5];

  float* out = (float*)d_out;
  float* out_mask = out + (size_t)NTOK * DDIM;
  float* out_ek   = out_mask + NTOK;

  uint32_t r1k0, r1k1, r2k0, r2k1;
  tf2x32(0u, 42u, 0u, 0u, &r1k0, &r1k1);
  tf2x32(0u, 42u, 0u, 1u, &r2k0, &r2k1);

  cudaFuncSetAttribute(gemm_logits_kernel,
                       cudaFuncAttributeMaxDynamicSharedMemorySize, DYN_SMEM);

  convX_kernel<<<(NTOK * DDIM / 4) / 256, 256>>>(X);
  convW_kernel<<<dim3(HDIM / 32, DDIM / 32), 256>>>(W1);
  gemm_logits_kernel<<<(NTOK / BM) * NHC, 512, DYN_SMEM>>>(b1, W2);
  topk_kernel<<<BATCH, 1024>>>(kl, out_ek, out_mask, r1k0, r1k1, r2k0, r2k1);
  refine_kernel<<<dim3(16, BATCH, 4), 256>>>(X, W1, b1, W2);
  fixup_kernel<<<BATCH, 64>>>(out_mask, r2k0, r2k1);
  scatter_kernel<<<NTOK, 256>>>(X, out);
}